// round 1
// baseline (speedup 1.0000x reference)
#include <cuda_runtime.h>
#include <cfloat>

// Problem: B=256 batches, each an N=256 x 256 fp32 score matrix.
// Greedy masked argmax assignment (sequential over 256 steps per batch).
// Output = hard permutation matrix (0.0 / 1.0), fp32, B*N*N elements.

#define BATCH 256
#define NN    256

__global__ void zero_out_kernel(float4* __restrict__ out, int n4) {
    int i = blockIdx.x * blockDim.x + threadIdx.x;
    if (i < n4) out[i] = make_float4(0.f, 0.f, 0.f, 0.f);
}

__global__ __launch_bounds__(256, 2)
void greedy_perm_kernel(const float* __restrict__ scores, float* __restrict__ out) {
    __shared__ float    s_val[NN];       // current max value per row (-FLT_MAX if assigned)
    __shared__ int      s_col[NN];       // argmax col per row
    __shared__ unsigned s_cmask[NN/32];  // masked-column bitmask
    __shared__ float    s_rv[8];
    __shared__ int      s_ri[8];
    __shared__ int      s_list[NN];
    __shared__ int      s_nlist;
    __shared__ int      s_selcol;

    const int b    = blockIdx.x;
    const int tid  = threadIdx.x;
    const int lane = tid & 31;
    const int warp = tid >> 5;
    const float* base  = scores + (size_t)b * NN * NN;
    float*       obase = out    + (size_t)b * NN * NN;

    if (tid < NN/32) s_cmask[tid] = 0u;

    // ---- init: per-row max over all 256 cols (one warp per row, coalesced) ----
    for (int row = warp; row < NN; row += 8) {
        const float* rp = base + (size_t)row * NN;
        float bv = -FLT_MAX; int bc = 0;
        #pragma unroll
        for (int k = 0; k < NN/32; k++) {
            int c = lane + 32 * k;
            float v = __ldg(rp + c);
            if (v > bv) { bv = v; bc = c; }   // increasing c: strict > keeps smallest col on tie
        }
        #pragma unroll
        for (int off = 16; off > 0; off >>= 1) {
            float ov = __shfl_xor_sync(0xffffffffu, bv, off);
            int   oc = __shfl_xor_sync(0xffffffffu, bc, off);
            if (ov > bv || (ov == bv && oc < bc)) { bv = ov; bc = oc; }
        }
        if (lane == 0) { s_val[row] = bv; s_col[row] = bc; }
    }
    __syncthreads();

    // ---- 256 sequential greedy steps ----
    for (int it = 0; it < NN; it++) {
        // block argmax over row maxima, tie-break = smallest row index
        float bv = s_val[tid]; int bi = tid;
        #pragma unroll
        for (int off = 16; off > 0; off >>= 1) {
            float ov = __shfl_xor_sync(0xffffffffu, bv, off);
            int   oi = __shfl_xor_sync(0xffffffffu, bi, off);
            if (ov > bv || (ov == bv && oi < bi)) { bv = ov; bi = oi; }
        }
        if (lane == 0) { s_rv[warp] = bv; s_ri[warp] = bi; }
        __syncthreads();

        if (tid == 0) {
            float gv = s_rv[0]; int gi = s_ri[0];
            #pragma unroll
            for (int w = 1; w < 8; w++) {
                float ov = s_rv[w]; int oi = s_ri[w];
                if (ov > gv || (ov == gv && oi < gi)) { gv = ov; gi = oi; }
            }
            int r = gi;
            int c = s_col[r];
            s_selcol = c;
            s_val[r] = -FLT_MAX;                 // row assigned
            s_cmask[c >> 5] |= (1u << (c & 31)); // col masked
            s_nlist = 0;
            obase[(size_t)r * NN + c] = 1.0f;
        }
        __syncthreads();

        if (it == NN - 1) break;

        // collect unassigned rows whose argmax column just got masked
        int c = s_selcol;
        if (s_val[tid] != -FLT_MAX && s_col[tid] == c) {
            int pos = atomicAdd(&s_nlist, 1);
            s_list[pos] = tid;
        }
        __syncthreads();

        // recompute those rows: one warp per row, 8 cols per lane (L2-resident)
        int nl = s_nlist;
        for (int j = warp; j < nl; j += 8) {
            int row = s_list[j];
            const float* rp = base + (size_t)row * NN;
            float v2 = -FLT_MAX; int c2 = 0;
            #pragma unroll
            for (int k = 0; k < NN/32; k++) {
                int cc = lane + 32 * k;
                bool masked = (s_cmask[cc >> 5] >> (cc & 31)) & 1u;
                float v = masked ? -FLT_MAX : __ldg(rp + cc);
                if (v > v2) { v2 = v; c2 = cc; }
            }
            #pragma unroll
            for (int off = 16; off > 0; off >>= 1) {
                float ov = __shfl_xor_sync(0xffffffffu, v2, off);
                int   oc = __shfl_xor_sync(0xffffffffu, c2, off);
                if (ov > v2 || (ov == v2 && oc < c2)) { v2 = ov; c2 = oc; }
            }
            if (lane == 0) { s_val[row] = v2; s_col[row] = c2; }
        }
        __syncthreads();
    }
}

extern "C" void kernel_launch(void* const* d_in, const int* in_sizes, int n_in,
                              void* d_out, int out_size) {
    const float* soft = (const float*)d_in[0];
    float* out = (float*)d_out;

    int n4 = out_size / 4;  // out_size = 256*256*256 floats
    zero_out_kernel<<<(n4 + 255) / 256, 256>>>((float4*)out, n4);
    greedy_perm_kernel<<<BATCH, 256>>>(soft, out);
}

// round 2
// speedup vs baseline: 1.0665x; 1.0665x over previous
#include <cuda_runtime.h>
#include <cstdint>

// B=256 batches, N=256. Greedy masked argmax assignment, one WARP per batch,
// fully warp-synchronous (no __syncthreads). State in registers:
//   - lane owns rows  row = j*32 + lane, j = 0..7:  vkey[j] (fp32 bits as uint,
//     0 = assigned/sentinel; softmax values are strictly > 0 so bits are
//     order-monotone), vcol[j] = argmax col over unmasked cols.
//   - cmask[8]: replicated 256-bit column mask; col c -> word c>>5, bit c&31.
// Selection uses HW warp reductions (REDUX) with exact reference tie-breaking:
// max value, then smallest flat index (smallest row, then smallest col).

#define NN 256
#define FULL 0xFFFFFFFFu

// Warp-cooperative masked row scan: returns (m = max key, c = smallest col
// attaining it) over unmasked cols of row pointer rp. Coalesced: lane reads
// cols k*32+lane (mask word = k (static), bit = lane).
__device__ __forceinline__ void scan_row(const float* __restrict__ rp,
                                         const unsigned cmask[8],
                                         int lane,
                                         unsigned& m_out, unsigned& c_out) {
    unsigned best = 0u;
    int bc = 0;
    #pragma unroll
    for (int k = 0; k < 8; k++) {
        float v = __ldg(rp + k * 32 + lane);
        unsigned key = ((cmask[k] >> lane) & 1u) ? 0u : __float_as_uint(v);
        if (key > best) { best = key; bc = k * 32 + lane; }  // increasing col: > keeps smallest
    }
    unsigned m = __reduce_max_sync(FULL, best);
    unsigned cand = (best == m) ? (unsigned)bc : 0xFFFFFFFFu;
    unsigned c = __reduce_min_sync(FULL, cand);
    m_out = m; c_out = c;
}

__global__ __launch_bounds__(32)
void greedy_perm_warp_kernel(const float* __restrict__ scores,
                             float* __restrict__ out) {
    const int b = blockIdx.x;
    const int lane = threadIdx.x;
    const float* base = scores + (size_t)b * NN * NN;
    float* obase = out + (size_t)b * NN * NN;

    unsigned vkey[8];
    int      vcol[8];
    unsigned cmask[8];
    #pragma unroll
    for (int k = 0; k < 8; k++) cmask[k] = 0u;

    // ---- init: per-row argmax (warp-cooperative, coalesced, rows pipelined) ----
    #pragma unroll
    for (int j = 0; j < 8; j++) {
        #pragma unroll 4
        for (int rr = 0; rr < 32; rr++) {
            int row = j * 32 + rr;
            unsigned m, c;
            scan_row(base + (size_t)row * NN, cmask, lane, m, c);
            if (lane == rr) { vkey[j] = m; vcol[j] = (int)c; }
        }
    }

    // ---- 256 sequential greedy steps, warp-synchronous ----
    for (int it = 0; it < NN; it++) {
        // local best over 8 owned rows (rows increase with j: > keeps smallest row)
        unsigned bk = 0u; int br = lane;
        #pragma unroll
        for (int j = 0; j < 8; j++) {
            unsigned k = vkey[j];
            if (k > bk) { bk = k; br = j * 32 + lane; }
        }
        // global max value, then smallest row among attainers
        unsigned m = __reduce_max_sync(FULL, bk);
        unsigned cand = (bk == m) ? (unsigned)br : 0xFFFFFFFFu;
        unsigned r = __reduce_min_sync(FULL, cand);

        int slot = (int)(r >> 5);
        int rl   = (int)(r & 31);

        // fetch the selected row's col from its owner lane
        int myc = vcol[0];
        #pragma unroll
        for (int j = 1; j < 8; j++) if (slot == j) myc = vcol[j];
        int c = __shfl_sync(FULL, myc, rl);

        // assign: kill row, mask col, write 1.0
        if (lane == rl) {
            #pragma unroll
            for (int j = 0; j < 8; j++) if (slot == j) vkey[j] = 0u;
        }
        #pragma unroll
        for (int k = 0; k < 8; k++)
            if (k == (c >> 5)) cmask[k] |= (1u << (c & 31));
        if (lane == 0)
            obase[(size_t)r * NN + c] = 1.0f;

        if (it == NN - 1) break;

        // rescan unassigned rows whose cached argmax col just got masked
        #pragma unroll
        for (int j = 0; j < 8; j++) {
            unsigned bal = __ballot_sync(FULL, vkey[j] != 0u && vcol[j] == c);
            while (bal) {
                int l2 = __ffs(bal) - 1;
                bal &= bal - 1;
                int row = j * 32 + l2;
                unsigned m2, c2;
                scan_row(base + (size_t)row * NN, cmask, lane, m2, c2);
                if (lane == l2) { vkey[j] = m2; vcol[j] = (int)c2; }
            }
        }
    }
}

extern "C" void kernel_launch(void* const* d_in, const int* in_sizes, int n_in,
                              void* d_out, int out_size) {
    const float* soft = (const float*)d_in[0];
    float* out = (float*)d_out;

    // zero the 64MB output (graph-capturable async memset), then fill the 1.0s
    cudaMemsetAsync(d_out, 0, (size_t)out_size * sizeof(float), 0);
    greedy_perm_warp_kernel<<<256, 32>>>(soft, out);
}